// round 6
// baseline (speedup 1.0000x reference)
#include <cuda_runtime.h>
#include <math_constants.h>

// SpatialAttention: out = x * hardsigmoid(conv3x3([mean_c(x); max_c(x)]))
// x: [16, 256, 128, 128] fp32, conv_w: [1, 2, 3, 3] fp32.
//
// Fused pipelined kernel, 1-batch chunks (16 MiB):
//   launch i:  reduce(chunk i) | conv(chunk i-1) | mul(chunk i-2)
// Live L2 set = 3 slices (48 MiB) + write stream << 126 MB L2, so mul's
// x reads are real L2 hits (CHUNK=2's 96+ MiB live set was thrashing).

#define BATCH 16
#define CH    256
#define HH    128
#define WW    128
#define HWSZ  (HH * WW)          // 16384
#define HW4   (HWSZ / 4)         // 4096 float4 cols per (b,c) plane
#define CHUNK 1                  // batches per chunk (16 MiB x-slice)
#define NCHNK (BATCH / CHUNK)    // 16 chunks

#define COLS_PER_BLK 16
#define NGRP  16                 // channel groups per reduce block
#define CPS   (CH / NGRP)        // 16 channels per group

#define R_BLK (CHUNK * HW4 / COLS_PER_BLK)   // 256 reduce blocks
#define C_BLK (CHUNK * HWSZ / 256)           // 64 conv blocks
#define M_BLK (CHUNK * CH * HW4 / 256)       // 4096 mul blocks

__device__ float g_avg[BATCH * HWSZ];
__device__ float g_max[BATCH * HWSZ];
__device__ float g_att[BATCH * HWSZ];

__global__ void __launch_bounds__(256, 6)
fused_kernel(const float* __restrict__ x, const float* __restrict__ wt,
             float* __restrict__ out, int b_red, int b_conv, int b_mul) {
    __shared__ float4 ssum[256];
    __shared__ float4 smax[256];

    int bid = blockIdx.x;

    if (bid < R_BLK) {
        // ---------------- reduce phase: chunk b_red ----------------
        if (b_red < 0) return;
        int colBase = bid * COLS_PER_BLK;
        int t     = threadIdx.x;
        int col_l = t & (COLS_PER_BLK - 1);
        int cg    = t >> 4;                     // 0..15 channel group
        int b     = b_red;                      // CHUNK==1

        const float4* xp = reinterpret_cast<const float4*>(x)
                         + (size_t)b * CH * HW4 + (size_t)cg * CPS * HW4
                         + colBase + col_l;

        float4 s = make_float4(0.f, 0.f, 0.f, 0.f);
        float4 m = make_float4(-CUDART_INF_F, -CUDART_INF_F, -CUDART_INF_F, -CUDART_INF_F);

        #pragma unroll 8
        for (int c = 0; c < CPS; c++) {
            float4 v = xp[c * HW4];
            s.x += v.x; s.y += v.y; s.z += v.z; s.w += v.w;
            m.x = fmaxf(m.x, v.x); m.y = fmaxf(m.y, v.y);
            m.z = fmaxf(m.z, v.z); m.w = fmaxf(m.w, v.w);
        }
        ssum[t] = s; smax[t] = m;
        __syncthreads();

        #pragma unroll
        for (int off = 128; off >= COLS_PER_BLK; off >>= 1) {
            if (t < off) {
                float4 s2 = ssum[t + off], m2 = smax[t + off];
                float4 sa = ssum[t],       ma = smax[t];
                sa.x += s2.x; sa.y += s2.y; sa.z += s2.z; sa.w += s2.w;
                ma.x = fmaxf(ma.x, m2.x); ma.y = fmaxf(ma.y, m2.y);
                ma.z = fmaxf(ma.z, m2.z); ma.w = fmaxf(ma.w, m2.w);
                ssum[t] = sa; smax[t] = ma;
            }
            __syncthreads();
        }

        if (t < COLS_PER_BLK) {
            const float inv = 1.0f / (float)CH;
            float4 sa = ssum[t], ma = smax[t];
            float4 a = make_float4(sa.x * inv, sa.y * inv, sa.z * inv, sa.w * inv);
            reinterpret_cast<float4*>(g_avg)[b * HW4 + colBase + t] = a;
            reinterpret_cast<float4*>(g_max)[b * HW4 + colBase + t] = ma;
        }
    } else if (bid < R_BLK + C_BLK) {
        // ---------------- conv phase: chunk b_conv ----------------
        if (b_conv < 0) return;
        int t  = (bid - R_BLK) * 256 + threadIdx.x;   // 0 .. HWSZ-1
        int hw = t & (HWSZ - 1);
        int h  = hw >> 7;
        int w  = hw & (WW - 1);
        int b  = b_conv;

        const float* __restrict__ A = g_avg + b * HWSZ;
        const float* __restrict__ M = g_max + b * HWSZ;

        float acc = 0.f;
        #pragma unroll
        for (int kh = 0; kh < 3; kh++) {
            int hh = h + kh - 1;
            if (hh < 0 || hh >= HH) continue;
            #pragma unroll
            for (int kw = 0; kw < 3; kw++) {
                int ww = w + kw - 1;
                if (ww < 0 || ww >= WW) continue;
                int o = hh * WW + ww;
                acc += __ldg(&wt[kh * 3 + kw])     * A[o]
                     + __ldg(&wt[9 + kh * 3 + kw]) * M[o];
            }
        }
        float y = fminf(fmaxf(acc + 3.0f, 0.0f), 6.0f) * (1.0f / 6.0f);
        g_att[b * HWSZ + hw] = y;
    } else {
        // ---------------- mul phase: chunk b_mul ----------------
        if (b_mul < 0) return;
        int t   = (bid - R_BLK - C_BLK) * 256 + threadIdx.x; // 0..CH*HW4-1
        int col = t & (HW4 - 1);
        int b   = b_mul;

        size_t gidx = (size_t)b * CH * HW4 + t;

        float4 v = __ldcs(reinterpret_cast<const float4*>(x) + gidx);
        float4 a = __ldg(reinterpret_cast<const float4*>(g_att) + (size_t)b * HW4 + col);

        v.x *= a.x; v.y *= a.y; v.z *= a.z; v.w *= a.w;
        __stcs(reinterpret_cast<float4*>(out) + gidx, v);
    }
}

extern "C" void kernel_launch(void* const* d_in, const int* in_sizes, int n_in,
                              void* d_out, int out_size) {
    const float* x  = (const float*)d_in[0];
    const float* wt = (const float*)d_in[1];
    float* out      = (float*)d_out;

    const int GRID = R_BLK + C_BLK + M_BLK;   // 4416 blocks

    for (int i = 0; i < NCHNK + 2; i++) {
        int br = (i < NCHNK)              ? i * CHUNK       : -1;
        int bc = (i >= 1 && i <= NCHNK)   ? (i - 1) * CHUNK : -1;
        int bm = (i >= 2)                 ? (i - 2) * CHUNK : -1;
        fused_kernel<<<GRID, 256>>>(x, wt, out, br, bc, bm);
    }
}